// round 9
// baseline (speedup 1.0000x reference)
#include <cuda_runtime.h>
#include <cuda_fp16.h>
#include <math.h>
#include <stdint.h>

// Problem constants
#define NB 32
#define NS 1024
#define NT 256
#define NBS 32768          // NB*NS rows
#define NCAT 1024          // 4*NT concatenated transition columns

// Static device scratch (allocation-free rule: __device__ globals)
__device__ float  g_Y[(size_t)NBS * NCAT];   // P @ Tcat   134.2 MB
__device__ __half g_Ph[NBS * NT];            // hi split of softmax(q)
__device__ __half g_Pl[NBS * NT];            // lo split
__device__ __half g_BhT[NCAT * NT];          // B[n][k]  (K-major, i.e. B^T rows)

// ---------------------------------------------------------------------------
// Build B (K-major): Bcat[k][n] stored transposed as BT[n][k]
//   n in [0,256):    T0[k][n]          (left  j=1)
//   n in [256,512):  T1[k][n-256]      (left  j=2)
//   n in [512,768):  T0[n-512][k]      (right j=1)
//   n in [768,1024): T1[n-768][k]      (right j=2)
// ---------------------------------------------------------------------------
__global__ void build_b_kernel(const float* __restrict__ trans) {
    int idx = blockIdx.x * blockDim.x + threadIdx.x;   // 0 .. 262143
    int n = idx >> 8;          // 0..1023
    int k = idx & 255;         // 0..255
    float v;
    if (n < 256)       v = trans[k * 256 + n];
    else if (n < 512)  v = trans[65536 + k * 256 + (n - 256)];
    else if (n < 768)  v = trans[(n - 512) * 256 + k];
    else               v = trans[65536 + (n - 768) * 256 + k];
    g_BhT[n * NT + k] = __float2half_rn(v);
}

// ---------------------------------------------------------------------------
// HMMA GEMM: g_Y[32768,1024] = (Ph+Pl)[32768,256] @ Bh^T
// mma.sync.aligned.m16n8k16.row.col.f32.f16.f16.f32.
// Block 128x128, 128 threads = 4 warps (2m x 2n), warp tile 64x64.
// ldmatrix.x4 fragment loads. K in 4 chunks of 64 halves (128B rows,
// XOR-(row&7)<<4 swizzle). 2 split passes per chunk (Ah*Bh + Al*Bh),
// 3 buffers (48KB): b0=Ah, b1=Bh, b2=Al. cp.async tile copies.
// ---------------------------------------------------------------------------
#define TILE_BYTES 16384                 // 128 rows x 128 B
#define GEMM_SMEM  (3 * TILE_BYTES)      // 48 KB, under default dyn-smem limit

__device__ __forceinline__ void mma16816(float* d, uint32_t a0, uint32_t a1,
                                         uint32_t a2, uint32_t a3,
                                         uint32_t b0, uint32_t b1) {
    asm volatile(
        "mma.sync.aligned.m16n8k16.row.col.f32.f16.f16.f32 "
        "{%0,%1,%2,%3}, {%4,%5,%6,%7}, {%8,%9}, {%0,%1,%2,%3};"
        : "+f"(d[0]), "+f"(d[1]), "+f"(d[2]), "+f"(d[3])
        : "r"(a0), "r"(a1), "r"(a2), "r"(a3), "r"(b0), "r"(b1));
}

__device__ __forceinline__ void ldsm_x4(uint32_t addr, uint32_t& r0, uint32_t& r1,
                                        uint32_t& r2, uint32_t& r3) {
    asm volatile("ldmatrix.sync.aligned.m8n8.x4.shared.b16 {%0,%1,%2,%3}, [%4];"
                 : "=r"(r0), "=r"(r1), "=r"(r2), "=r"(r3) : "r"(addr));
}

__device__ __forceinline__ void cp16(uint32_t dst, const void* src) {
    asm volatile("cp.async.cg.shared.global [%0], [%1], 16;"
                 :: "r"(dst), "l"(src) : "memory");
}

// One split pass over a 64-half K chunk. Warp tile 64x64:
// 4 m-frags (16 rows) x 8 n-frags (8 cols), 4 k16 steps.
__device__ __forceinline__ void mma_pass(uint32_t aB, uint32_t bB,
                                         float acc[4][8][4],
                                         int wm, int wn, int lane) {
    int lr = lane & 7;
    int quad = lane >> 3;              // 0..3: ldmatrix source-row group
    int rlow = (quad & 1) * 8 + lr;    // row within 16-row frag
    int khb = (quad >> 1) * 16;        // 0 or 16 bytes (k-half)

#pragma unroll
    for (int ks = 0; ks < 4; ++ks) {
        uint32_t kb = (uint32_t)(ks * 32 + khb);
        // A fragments: 4 x ldmatrix.x4
        uint32_t af[4][4];
#pragma unroll
        for (int mf = 0; mf < 4; ++mf) {
            uint32_t row = (uint32_t)(wm * 64 + mf * 16 + rlow);
            uint32_t addr = aB + row * 128 + (kb ^ ((row & 7) << 4));
            ldsm_x4(addr, af[mf][0], af[mf][1], af[mf][2], af[mf][3]);
        }
        // B fragments: 4 x ldmatrix.x4, each covers two 8-col n-frags
        uint32_t bf[8][2];
#pragma unroll
        for (int i = 0; i < 4; ++i) {
            uint32_t row = (uint32_t)(wn * 64 + i * 16 + rlow);
            uint32_t addr = bB + row * 128 + (kb ^ ((row & 7) << 4));
            ldsm_x4(addr, bf[2 * i][0], bf[2 * i + 1][0],
                    bf[2 * i][1], bf[2 * i + 1][1]);
        }
#pragma unroll
        for (int mf = 0; mf < 4; ++mf)
#pragma unroll
            for (int nf = 0; nf < 8; ++nf)
                mma16816(acc[mf][nf], af[mf][0], af[mf][1], af[mf][2],
                         af[mf][3], bf[nf][0], bf[nf][1]);
    }
}

// async-copy one 128-row x 128B tile gmem -> swizzled smem, coalesced:
// thread t handles (row = t>>3 + 16p, 16B col = (t&7)*16).
__device__ __forceinline__ void copy_tile_async(uint32_t dst, const __half* srcBase,
                                                int row0, int k0, int tid) {
    int trow = tid >> 3;
    uint32_t tcol = (uint32_t)((tid & 7) * 16);
#pragma unroll
    for (int p = 0; p < 8; ++p) {
        int row = trow + p * 16;
        const void* src = (const char*)(srcBase + (size_t)(row0 + row) * NT + k0) + tcol;
        cp16(dst + (uint32_t)(row * 128) + (tcol ^ ((uint32_t)(row & 7) << 4)), src);
    }
}

__global__ void __launch_bounds__(128, 2) gemm_hmma_kernel() {
    extern __shared__ char smem[];
    uint32_t sb = (uint32_t)__cvta_generic_to_shared(smem);
    uint32_t u0 = sb, u1 = sb + TILE_BYTES, u2 = sb + 2 * TILE_BYTES;

    int tid  = threadIdx.x;
    int wid  = tid >> 5;
    int lane = tid & 31;
    int wm = wid & 1;          // 0..1 : 64-row half
    int wn = wid >> 1;         // 0..1 : 64-col half
    int g  = lane >> 2;        // 0..7
    int tg = lane & 3;         // 0..3

    int m0 = blockIdx.y * 128;
    int n0 = blockIdx.x * 128;

    float acc[4][8][4];
#pragma unroll
    for (int i = 0; i < 4; i++)
#pragma unroll
        for (int j = 0; j < 8; j++)
#pragma unroll
            for (int r = 0; r < 4; r++) acc[i][j][r] = 0.0f;

    for (int chunk = 0; chunk < 4; ++chunk) {
        int k0 = chunk * 64;           // half index
        if (chunk) __syncthreads();    // all warps done reading smem
        copy_tile_async(u0, g_Ph,  m0, k0, tid);
        copy_tile_async(u1, g_BhT, n0, k0, tid);
        copy_tile_async(u2, g_Pl,  m0, k0, tid);
        asm volatile("cp.async.commit_group;" ::: "memory");
        asm volatile("cp.async.wait_group 0;" ::: "memory");
        __syncthreads();

        mma_pass(u0, u1, acc, wm, wn, lane);   // Ah * Bh
        mma_pass(u2, u1, acc, wm, wn, lane);   // Al * Bh
    }

    // epilogue: per frag c0={g,2tg}, c1={g,2tg+1}, c2={g+8,2tg}, c3={g+8,2tg+1}
#pragma unroll
    for (int mf = 0; mf < 4; ++mf) {
#pragma unroll
        for (int nf = 0; nf < 8; ++nf) {
            int mrow = m0 + wm * 64 + mf * 16 + g;
            int col  = n0 + wn * 64 + nf * 8 + tg * 2;
            float* p = g_Y + (size_t)mrow * NCAT + col;
            *(float2*)p = make_float2(acc[mf][nf][0], acc[mf][nf][1]);
            *(float2*)(p + (size_t)8 * NCAT) = make_float2(acc[mf][nf][2], acc[mf][nf][3]);
        }
    }
}

// ---------------------------------------------------------------------------
// Combine: warp per row, 8 tags per thread, shuffle-only softmax.
// mode 0: q = unary*mask              -> softmax -> (Ph,Pl)
// mode 1: q = (unary*mask + msg)*mask -> softmax -> (Ph,Pl)
// mode 2: same q -> write to out (final)
// ---------------------------------------------------------------------------
__global__ void __launch_bounds__(256) combine_kernel(
    const float* __restrict__ unary_score,
    const float* __restrict__ mask,
    const float* __restrict__ start_t,   // [2,256]
    const float* __restrict__ end_t,     // [2,256]
    const int*   __restrict__ lengths,   // [32]
    float* __restrict__ out,
    int mode)
{
    int warp = threadIdx.x >> 5;
    int lane = threadIdx.x & 31;
    int row = blockIdx.x * 8 + warp;     // b*NS + s
    int b = row >> 10;
    int s = row & 1023;

    float m = mask[row];
    size_t base = (size_t)row * NT + lane;

    float q[8];
#pragma unroll
    for (int j = 0; j < 8; ++j) q[j] = unary_score[base + j * 32] * m;

    if (mode != 0) {
        float msg[8];
#pragma unroll
        for (int j = 0; j < 8; ++j) msg[j] = 0.0f;
        if (s >= 1) {
            const float* p = g_Y + (size_t)(row - 1) * NCAT + lane;
#pragma unroll
            for (int j = 0; j < 8; ++j) msg[j] += p[j * 32];
        }
        if (s >= 2) {
            const float* p = g_Y + (size_t)(row - 2) * NCAT + 256 + lane;
#pragma unroll
            for (int j = 0; j < 8; ++j) msg[j] += p[j * 32];
        }
        if (s <= NS - 2) {
            const float* p = g_Y + (size_t)(row + 1) * NCAT + 512 + lane;
#pragma unroll
            for (int j = 0; j < 8; ++j) msg[j] += p[j * 32];
        }
        if (s <= NS - 3) {
            const float* p = g_Y + (size_t)(row + 2) * NCAT + 768 + lane;
#pragma unroll
            for (int j = 0; j < 8; ++j) msg[j] += p[j * 32];
        }
        int len = __ldg(&lengths[b]);
        if (s == len - 1) {
#pragma unroll
            for (int j = 0; j < 8; ++j) msg[j] += end_t[lane + j * 32];
        }
        if (s == len - 2) {
#pragma unroll
            for (int j = 0; j < 8; ++j) msg[j] += end_t[256 + lane + j * 32];
        }
        if (s < 2) {
#pragma unroll
            for (int j = 0; j < 8; ++j) msg[j] += start_t[s * 256 + lane + j * 32];
        }
#pragma unroll
        for (int j = 0; j < 8; ++j) q[j] = (q[j] + msg[j]) * m;
    }

    if (mode == 2) {
#pragma unroll
        for (int j = 0; j < 8; ++j) out[base + j * 32] = q[j];
        return;
    }

    // softmax over 256 (8 per thread x 32 lanes), shuffle reductions only
    float mx = q[0];
#pragma unroll
    for (int j = 1; j < 8; ++j) mx = fmaxf(mx, q[j]);
#pragma unroll
    for (int o = 16; o; o >>= 1) mx = fmaxf(mx, __shfl_xor_sync(0xffffffffu, mx, o));

    float e[8];
    float sum = 0.0f;
#pragma unroll
    for (int j = 0; j < 8; ++j) { e[j] = __expf(q[j] - mx); sum += e[j]; }
#pragma unroll
    for (int o = 16; o; o >>= 1) sum += __shfl_xor_sync(0xffffffffu, sum, o);
    float rinv = __frcp_rn(sum);

#pragma unroll
    for (int j = 0; j < 8; ++j) {
        float p = e[j] * rinv;
        __half h = __float2half_rn(p);
        __half l = __float2half_rn(p - __half2float(h));
        g_Ph[base + j * 32] = h;
        g_Pl[base + j * 32] = l;
    }
}

// ---------------------------------------------------------------------------
// Input order: token_feats, unary_score, mask, transitions,
//              start_transitions, end_transitions, lengths
// ---------------------------------------------------------------------------
extern "C" void kernel_launch(void* const* d_in, const int* in_sizes, int n_in,
                              void* d_out, int out_size) {
    const float* unary   = (const float*)d_in[1];
    const float* mask    = (const float*)d_in[2];
    const float* trans   = (const float*)d_in[3];
    const float* start_t = (const float*)d_in[4];
    const float* end_t   = (const float*)d_in[5];
    const int*   lengths = (const int*)d_in[6];
    float* out = (float*)d_out;

    build_b_kernel<<<1024, 256>>>(trans);

    // initial P = softmax(unary * mask)
    combine_kernel<<<NBS / 8, 256>>>(unary, mask, start_t, end_t, lengths, out, 0);

    dim3 gemm_grid(NCAT / 128, NBS / 128);   // (8, 256)
    for (int it = 0; it < 3; ++it) {
        gemm_hmma_kernel<<<gemm_grid, 128, GEMM_SMEM>>>();
        int mode = (it == 2) ? 2 : 1;
        combine_kernel<<<NBS / 8, 256>>>(unary, mask, start_t, end_t, lengths, out, mode);
    }
}

// round 10
// speedup vs baseline: 1.3919x; 1.3919x over previous
#include <cuda_runtime.h>
#include <cuda_fp16.h>
#include <math.h>
#include <stdint.h>

// Problem constants
#define NB 32
#define NS 1024
#define NT 256
#define NBS 32768          // NB*NS rows
#define NCAT 1024          // 4*NT concatenated transition columns

// Static device scratch (allocation-free rule: __device__ globals)
__device__ float  g_Y[(size_t)NBS * NCAT];   // P @ Tcat   134.2 MB
__device__ __half g_Ph[NBS * NT];            // hi split of softmax(q)
__device__ __half g_Pl[NBS * NT];            // lo split
__device__ __half g_BhT[NCAT * NT];          // B[n][k]  (K-major, i.e. B^T rows)

// ---------------------------------------------------------------------------
// Build B (K-major): Bcat[k][n] stored transposed as BT[n][k]
//   n in [0,256):    T0[k][n]          (left  j=1)
//   n in [256,512):  T1[k][n-256]      (left  j=2)
//   n in [512,768):  T0[n-512][k]      (right j=1)
//   n in [768,1024): T1[n-768][k]      (right j=2)
// ---------------------------------------------------------------------------
__global__ void build_b_kernel(const float* __restrict__ trans) {
    int idx = blockIdx.x * blockDim.x + threadIdx.x;   // 0 .. 262143
    int n = idx >> 8;          // 0..1023
    int k = idx & 255;         // 0..255
    float v;
    if (n < 256)       v = trans[k * 256 + n];
    else if (n < 512)  v = trans[65536 + k * 256 + (n - 256)];
    else if (n < 768)  v = trans[(n - 512) * 256 + k];
    else               v = trans[65536 + (n - 768) * 256 + k];
    g_BhT[n * NT + k] = __float2half_rn(v);
}

// ---------------------------------------------------------------------------
// HMMA GEMM: g_Y[32768,1024] = (Ph+Pl)[32768,256] @ Bh^T
// mma.sync.aligned.m16n8k16.row.col.f32.f16.f16.f32.
// Block 128x128, 128 threads = 4 warps (2m x 2n), warp tile 64x64.
// K in 8 chunks of 32 halves (64B rows). 2-stage cp.async pipeline:
// 2 stages x 3 tiles (Ah, Bh, Al) x 8KB = 48KB smem.
// Swizzle: 16B unit at logical col c of row r lives at c ^ (((r>>1)&3)<<4).
// ---------------------------------------------------------------------------
#define TILE32_BYTES 8192                // 128 rows x 64 B
#define STAGE_BYTES  (3 * TILE32_BYTES)  // Ah, Bh, Al
#define GEMM_SMEM    (2 * STAGE_BYTES)   // 48 KB

__device__ __forceinline__ void mma16816(float* d, uint32_t a0, uint32_t a1,
                                         uint32_t a2, uint32_t a3,
                                         uint32_t b0, uint32_t b1) {
    asm volatile(
        "mma.sync.aligned.m16n8k16.row.col.f32.f16.f16.f32 "
        "{%0,%1,%2,%3}, {%4,%5,%6,%7}, {%8,%9}, {%0,%1,%2,%3};"
        : "+f"(d[0]), "+f"(d[1]), "+f"(d[2]), "+f"(d[3])
        : "r"(a0), "r"(a1), "r"(a2), "r"(a3), "r"(b0), "r"(b1));
}

__device__ __forceinline__ void ldsm_x4(uint32_t addr, uint32_t& r0, uint32_t& r1,
                                        uint32_t& r2, uint32_t& r3) {
    asm volatile("ldmatrix.sync.aligned.m8n8.x4.shared.b16 {%0,%1,%2,%3}, [%4];"
                 : "=r"(r0), "=r"(r1), "=r"(r2), "=r"(r3) : "r"(addr));
}

__device__ __forceinline__ void cp16(uint32_t dst, const void* src) {
    asm volatile("cp.async.cg.shared.global [%0], [%1], 16;"
                 :: "r"(dst), "l"(src) : "memory");
}

__device__ __forceinline__ uint32_t sw32(uint32_t row) {   // 64B-row swizzle
    return ((row >> 1) & 3u) << 4;
}

// One split pass over a 32-half K chunk. Warp tile 64x64:
// 4 m-frags x 8 n-frags, 2 k16 steps.
__device__ __forceinline__ void mma_pass32(uint32_t aB, uint32_t bB,
                                           float acc[4][8][4],
                                           int wm, int wn, int lane) {
    int lr = lane & 7;
    int quad = lane >> 3;              // 0..3: ldmatrix source-row group
    int rlow = (quad & 1) * 8 + lr;    // row within 16-row frag
    int khb = (quad >> 1) * 16;        // 0 or 16 bytes (k8 within k16)

#pragma unroll
    for (int ks = 0; ks < 2; ++ks) {
        uint32_t kb = (uint32_t)(ks * 32 + khb);
        uint32_t af[4][4];
#pragma unroll
        for (int mf = 0; mf < 4; ++mf) {
            uint32_t row = (uint32_t)(wm * 64 + mf * 16 + rlow);
            uint32_t addr = aB + row * 64 + (kb ^ sw32(row));
            ldsm_x4(addr, af[mf][0], af[mf][1], af[mf][2], af[mf][3]);
        }
        uint32_t bf[8][2];
#pragma unroll
        for (int i = 0; i < 4; ++i) {
            uint32_t row = (uint32_t)(wn * 64 + i * 16 + rlow);
            uint32_t addr = bB + row * 64 + (kb ^ sw32(row));
            ldsm_x4(addr, bf[2 * i][0], bf[2 * i + 1][0],
                    bf[2 * i][1], bf[2 * i + 1][1]);
        }
#pragma unroll
        for (int mf = 0; mf < 4; ++mf)
#pragma unroll
            for (int nf = 0; nf < 8; ++nf)
                mma16816(acc[mf][nf], af[mf][0], af[mf][1], af[mf][2],
                         af[mf][3], bf[nf][0], bf[nf][1]);
    }
}

// async-copy one 128-row x 64B tile gmem -> swizzled smem.
// thread t: rows t>>2 + 32p, 16B col (t&3)*16. Lanes 0-3 cover one 64B gmem
// segment (contiguous); warp covers 8 rows per p.
__device__ __forceinline__ void copy_tile32_async(uint32_t dst, const __half* srcBase,
                                                  int row0, int k0, int tid) {
    int r0 = tid >> 2;
    uint32_t col = (uint32_t)((tid & 3) * 16);
#pragma unroll
    for (int p = 0; p < 4; ++p) {
        int row = r0 + p * 32;
        const void* src = (const char*)(srcBase + (size_t)(row0 + row) * NT + k0) + col;
        cp16(dst + (uint32_t)(row * 64) + (col ^ sw32((uint32_t)row)), src);
    }
}

__global__ void __launch_bounds__(128, 2) gemm_hmma_kernel() {
    extern __shared__ char smem[];
    uint32_t sb = (uint32_t)__cvta_generic_to_shared(smem);

    int tid  = threadIdx.x;
    int wid  = tid >> 5;
    int lane = tid & 31;
    int wm = wid & 1;          // 0..1 : 64-row half
    int wn = wid >> 1;         // 0..1 : 64-col half
    int g  = lane >> 2;        // 0..7
    int tg = lane & 3;         // 0..3

    int m0 = blockIdx.y * 128;
    int n0 = blockIdx.x * 128;

    float acc[4][8][4];
#pragma unroll
    for (int i = 0; i < 4; i++)
#pragma unroll
        for (int j = 0; j < 8; j++)
#pragma unroll
            for (int r = 0; r < 4; r++) acc[i][j][r] = 0.0f;

    // prologue: prefetch chunk 0 into stage 0
    {
        uint32_t st = sb;
        copy_tile32_async(st,                     g_Ph,  m0, 0, tid);
        copy_tile32_async(st + TILE32_BYTES,      g_BhT, n0, 0, tid);
        copy_tile32_async(st + 2 * TILE32_BYTES,  g_Pl,  m0, 0, tid);
        asm volatile("cp.async.commit_group;" ::: "memory");
    }

    for (int c = 0; c < 8; ++c) {
        uint32_t cur = sb + (uint32_t)(c & 1) * STAGE_BYTES;
        if (c < 7) {
            // prefetch c+1 into the other stage (consumed+synced in iter c-1)
            uint32_t nxt = sb + (uint32_t)((c + 1) & 1) * STAGE_BYTES;
            int k0 = (c + 1) * 32;
            copy_tile32_async(nxt,                    g_Ph,  m0, k0, tid);
            copy_tile32_async(nxt + TILE32_BYTES,     g_BhT, n0, k0, tid);
            copy_tile32_async(nxt + 2 * TILE32_BYTES, g_Pl,  m0, k0, tid);
            asm volatile("cp.async.commit_group;" ::: "memory");
            asm volatile("cp.async.wait_group 1;" ::: "memory");
        } else {
            asm volatile("cp.async.wait_group 0;" ::: "memory");
        }
        __syncthreads();

        mma_pass32(cur, cur + TILE32_BYTES, acc, wm, wn, lane);                    // Ah*Bh
        mma_pass32(cur + 2 * TILE32_BYTES, cur + TILE32_BYTES, acc, wm, wn, lane); // Al*Bh
        __syncthreads();   // all warps done with 'cur' before it is refilled
    }

    // epilogue: per frag c0={g,2tg}, c1={g,2tg+1}, c2={g+8,2tg}, c3={g+8,2tg+1}
#pragma unroll
    for (int mf = 0; mf < 4; ++mf) {
#pragma unroll
        for (int nf = 0; nf < 8; ++nf) {
            int mrow = m0 + wm * 64 + mf * 16 + g;
            int col  = n0 + wn * 64 + nf * 8 + tg * 2;
            float* p = g_Y + (size_t)mrow * NCAT + col;
            *(float2*)p = make_float2(acc[mf][nf][0], acc[mf][nf][1]);
            *(float2*)(p + (size_t)8 * NCAT) = make_float2(acc[mf][nf][2], acc[mf][nf][3]);
        }
    }
}

// ---------------------------------------------------------------------------
// Combine: warp per row, 8 tags per thread, shuffle-only softmax.
// mode 0: q = unary*mask              -> softmax -> (Ph,Pl)
// mode 1: q = (unary*mask + msg)*mask -> softmax -> (Ph,Pl)
// mode 2: same q -> write to out (final)
// ---------------------------------------------------------------------------
__global__ void __launch_bounds__(256) combine_kernel(
    const float* __restrict__ unary_score,
    const float* __restrict__ mask,
    const float* __restrict__ start_t,   // [2,256]
    const float* __restrict__ end_t,     // [2,256]
    const int*   __restrict__ lengths,   // [32]
    float* __restrict__ out,
    int mode)
{
    int warp = threadIdx.x >> 5;
    int lane = threadIdx.x & 31;
    int row = blockIdx.x * 8 + warp;     // b*NS + s
    int b = row >> 10;
    int s = row & 1023;

    float m = mask[row];
    size_t base = (size_t)row * NT + lane;

    float q[8];
#pragma unroll
    for (int j = 0; j < 8; ++j) q[j] = unary_score[base + j * 32] * m;

    if (mode != 0) {
        float msg[8];
#pragma unroll
        for (int j = 0; j < 8; ++j) msg[j] = 0.0f;
        if (s >= 1) {
            const float* p = g_Y + (size_t)(row - 1) * NCAT + lane;
#pragma unroll
            for (int j = 0; j < 8; ++j) msg[j] += p[j * 32];
        }
        if (s >= 2) {
            const float* p = g_Y + (size_t)(row - 2) * NCAT + 256 + lane;
#pragma unroll
            for (int j = 0; j < 8; ++j) msg[j] += p[j * 32];
        }
        if (s <= NS - 2) {
            const float* p = g_Y + (size_t)(row + 1) * NCAT + 512 + lane;
#pragma unroll
            for (int j = 0; j < 8; ++j) msg[j] += p[j * 32];
        }
        if (s <= NS - 3) {
            const float* p = g_Y + (size_t)(row + 2) * NCAT + 768 + lane;
#pragma unroll
            for (int j = 0; j < 8; ++j) msg[j] += p[j * 32];
        }
        int len = __ldg(&lengths[b]);
        if (s == len - 1) {
#pragma unroll
            for (int j = 0; j < 8; ++j) msg[j] += end_t[lane + j * 32];
        }
        if (s == len - 2) {
#pragma unroll
            for (int j = 0; j < 8; ++j) msg[j] += end_t[256 + lane + j * 32];
        }
        if (s < 2) {
#pragma unroll
            for (int j = 0; j < 8; ++j) msg[j] += start_t[s * 256 + lane + j * 32];
        }
#pragma unroll
        for (int j = 0; j < 8; ++j) q[j] = (q[j] + msg[j]) * m;
    }

    if (mode == 2) {
#pragma unroll
        for (int j = 0; j < 8; ++j) out[base + j * 32] = q[j];
        return;
    }

    // softmax over 256 (8 per thread x 32 lanes), shuffle reductions only
    float mx = q[0];
#pragma unroll
    for (int j = 1; j < 8; ++j) mx = fmaxf(mx, q[j]);
#pragma unroll
    for (int o = 16; o; o >>= 1) mx = fmaxf(mx, __shfl_xor_sync(0xffffffffu, mx, o));

    float e[8];
    float sum = 0.0f;
#pragma unroll
    for (int j = 0; j < 8; ++j) { e[j] = __expf(q[j] - mx); sum += e[j]; }
#pragma unroll
    for (int o = 16; o; o >>= 1) sum += __shfl_xor_sync(0xffffffffu, sum, o);
    float rinv = __frcp_rn(sum);

#pragma unroll
    for (int j = 0; j < 8; ++j) {
        float p = e[j] * rinv;
        __half h = __float2half_rn(p);
        __half l = __float2half_rn(p - __half2float(h));
        g_Ph[base + j * 32] = h;
        g_Pl[base + j * 32] = l;
    }
}

// ---------------------------------------------------------------------------
// Input order: token_feats, unary_score, mask, transitions,
//              start_transitions, end_transitions, lengths
// ---------------------------------------------------------------------------
extern "C" void kernel_launch(void* const* d_in, const int* in_sizes, int n_in,
                              void* d_out, int out_size) {
    const float* unary   = (const float*)d_in[1];
    const float* mask    = (const float*)d_in[2];
    const float* trans   = (const float*)d_in[3];
    const float* start_t = (const float*)d_in[4];
    const float* end_t   = (const float*)d_in[5];
    const int*   lengths = (const int*)d_in[6];
    float* out = (float*)d_out;

    build_b_kernel<<<1024, 256>>>(trans);

    // initial P = softmax(unary * mask)
    combine_kernel<<<NBS / 8, 256>>>(unary, mask, start_t, end_t, lengths, out, 0);

    dim3 gemm_grid(NCAT / 128, NBS / 128);   // (8, 256)
    for (int it = 0; it < 3; ++it) {
        gemm_hmma_kernel<<<gemm_grid, 128, GEMM_SMEM>>>();
        int mode = (it == 2) ? 2 : 1;
        combine_kernel<<<NBS / 8, 256>>>(unary, mask, start_t, end_t, lengths, out, mode);
    }
}

// round 12
// speedup vs baseline: 2.0105x; 1.4445x over previous
#include <cuda_runtime.h>
#include <cuda_fp16.h>
#include <math.h>
#include <stdint.h>

// Problem constants
#define NB 32
#define NS 1024
#define NT 256
#define NBS 32768          // NB*NS rows
#define NCAT 1024          // 4*NT concatenated transition columns

// Static device scratch (allocation-free rule: __device__ globals)
__device__ float  g_Y[(size_t)NBS * NCAT];   // P @ Tcat   134.2 MB
__device__ __half g_Ph[NBS * NT];            // fp16 softmax(q)
__device__ __half g_BhT[NCAT * NT];          // B[n][k]  (K-major, i.e. B^T rows)

// ---------------------------------------------------------------------------
// Build B (K-major): Bcat[k][n] stored transposed as BT[n][k]
//   n in [0,256):    T0[k][n]          (left  j=1)
//   n in [256,512):  T1[k][n-256]      (left  j=2)
//   n in [512,768):  T0[n-512][k]      (right j=1)
//   n in [768,1024): T1[n-768][k]      (right j=2)
// ---------------------------------------------------------------------------
__global__ void build_b_kernel(const float* __restrict__ trans) {
    int idx = blockIdx.x * blockDim.x + threadIdx.x;   // 0 .. 262143
    int n = idx >> 8;          // 0..1023
    int k = idx & 255;         // 0..255
    float v;
    if (n < 256)       v = trans[k * 256 + n];
    else if (n < 512)  v = trans[65536 + k * 256 + (n - 256)];
    else if (n < 768)  v = trans[(n - 512) * 256 + k];
    else               v = trans[65536 + (n - 768) * 256 + k];
    g_BhT[n * NT + k] = __float2half_rn(v);
}

// ---------------------------------------------------------------------------
// HMMA GEMM: g_Y[32768,1024] = Ph[32768,256] @ Bh^T
// mma.sync.aligned.m16n8k16.row.col.f32.f16.f16.f32.
// Block 128x128, 128 threads = 4 warps (2m x 2n), warp tile 64x64.
// K in 8 chunks of 32 halves (64B rows). 3-stage cp.async pipeline:
// 3 stages x 2 tiles (A, B) x 8KB = 48KB smem.
// Swizzle: 16B unit at logical col c of row r lives at c ^ (((r>>1)&3)<<4).
// ---------------------------------------------------------------------------
#define TILE32_BYTES 8192                // 128 rows x 64 B
#define STAGE_BYTES  (2 * TILE32_BYTES)  // A, B
#define GEMM_SMEM    (3 * STAGE_BYTES)   // 48 KB

__device__ __forceinline__ void mma16816(float* d, uint32_t a0, uint32_t a1,
                                         uint32_t a2, uint32_t a3,
                                         uint32_t b0, uint32_t b1) {
    asm volatile(
        "mma.sync.aligned.m16n8k16.row.col.f32.f16.f16.f32 "
        "{%0,%1,%2,%3}, {%4,%5,%6,%7}, {%8,%9}, {%0,%1,%2,%3};"
        : "+f"(d[0]), "+f"(d[1]), "+f"(d[2]), "+f"(d[3])
        : "r"(a0), "r"(a1), "r"(a2), "r"(a3), "r"(b0), "r"(b1));
}

__device__ __forceinline__ void ldsm_x4(uint32_t addr, uint32_t& r0, uint32_t& r1,
                                        uint32_t& r2, uint32_t& r3) {
    asm volatile("ldmatrix.sync.aligned.m8n8.x4.shared.b16 {%0,%1,%2,%3}, [%4];"
                 : "=r"(r0), "=r"(r1), "=r"(r2), "=r"(r3) : "r"(addr));
}

__device__ __forceinline__ void cp16(uint32_t dst, const void* src) {
    asm volatile("cp.async.cg.shared.global [%0], [%1], 16;"
                 :: "r"(dst), "l"(src) : "memory");
}

__device__ __forceinline__ uint32_t sw32(uint32_t row) {   // 64B-row swizzle
    return ((row >> 1) & 3u) << 4;
}

// One pass over a 32-half K chunk. Warp tile 64x64: 4 m-frags x 8 n-frags,
// 2 k16 steps.
__device__ __forceinline__ void mma_pass32(uint32_t aB, uint32_t bB,
                                           float acc[4][8][4],
                                           int wm, int wn, int lane) {
    int lr = lane & 7;
    int quad = lane >> 3;              // 0..3: ldmatrix source-row group
    int rlow = (quad & 1) * 8 + lr;    // row within 16-row frag
    int khb = (quad >> 1) * 16;        // 0 or 16 bytes (k8 within k16)

#pragma unroll
    for (int ks = 0; ks < 2; ++ks) {
        uint32_t kb = (uint32_t)(ks * 32 + khb);
        uint32_t af[4][4];
#pragma unroll
        for (int mf = 0; mf < 4; ++mf) {
            uint32_t row = (uint32_t)(wm * 64 + mf * 16 + rlow);
            uint32_t addr = aB + row * 64 + (kb ^ sw32(row));
            ldsm_x4(addr, af[mf][0], af[mf][1], af[mf][2], af[mf][3]);
        }
        uint32_t bf[8][2];
#pragma unroll
        for (int i = 0; i < 4; ++i) {
            uint32_t row = (uint32_t)(wn * 64 + i * 16 + rlow);
            uint32_t addr = bB + row * 64 + (kb ^ sw32(row));
            ldsm_x4(addr, bf[2 * i][0], bf[2 * i + 1][0],
                    bf[2 * i][1], bf[2 * i + 1][1]);
        }
#pragma unroll
        for (int mf = 0; mf < 4; ++mf)
#pragma unroll
            for (int nf = 0; nf < 8; ++nf)
                mma16816(acc[mf][nf], af[mf][0], af[mf][1], af[mf][2],
                         af[mf][3], bf[nf][0], bf[nf][1]);
    }
}

// async-copy one 128-row x 64B tile gmem -> swizzled smem.
// thread t: rows t>>2 + 32p, 16B col (t&3)*16.
__device__ __forceinline__ void copy_tile32_async(uint32_t dst, const __half* srcBase,
                                                  int row0, int k0, int tid) {
    int r0 = tid >> 2;
    uint32_t col = (uint32_t)((tid & 3) * 16);
#pragma unroll
    for (int p = 0; p < 4; ++p) {
        int row = r0 + p * 32;
        const void* src = (const char*)(srcBase + (size_t)(row0 + row) * NT + k0) + col;
        cp16(dst + (uint32_t)(row * 64) + (col ^ sw32((uint32_t)row)), src);
    }
}

__device__ __forceinline__ void prefetch_chunk(uint32_t sb, int c,
                                               int m0, int n0, int tid) {
    uint32_t st = sb + (uint32_t)(c % 3) * STAGE_BYTES;
    int k0 = c * 32;
    copy_tile32_async(st,                g_Ph,  m0, k0, tid);
    copy_tile32_async(st + TILE32_BYTES, g_BhT, n0, k0, tid);
    asm volatile("cp.async.commit_group;" ::: "memory");
}

__global__ void __launch_bounds__(128, 2) gemm_hmma_kernel() {
    extern __shared__ char smem[];
    uint32_t sb = (uint32_t)__cvta_generic_to_shared(smem);

    int tid  = threadIdx.x;
    int wid  = tid >> 5;
    int lane = tid & 31;
    int wm = wid & 1;          // 0..1 : 64-row half
    int wn = wid >> 1;         // 0..1 : 64-col half
    int g  = lane >> 2;        // 0..7
    int tg = lane & 3;         // 0..3

    int m0 = blockIdx.y * 128;
    int n0 = blockIdx.x * 128;

    float acc[4][8][4];
#pragma unroll
    for (int i = 0; i < 4; i++)
#pragma unroll
        for (int j = 0; j < 8; j++)
#pragma unroll
            for (int r = 0; r < 4; r++) acc[i][j][r] = 0.0f;

    // prologue: prefetch chunks 0,1,2 into stages 0,1,2
    prefetch_chunk(sb, 0, m0, n0, tid);
    prefetch_chunk(sb, 1, m0, n0, tid);
    prefetch_chunk(sb, 2, m0, n0, tid);

    for (int c = 0; c < 8; ++c) {
        // wait until chunk c has landed (keep newest 2 groups in flight)
        if (c < 6)      asm volatile("cp.async.wait_group 2;" ::: "memory");
        else if (c == 6) asm volatile("cp.async.wait_group 1;" ::: "memory");
        else             asm volatile("cp.async.wait_group 0;" ::: "memory");
        __syncthreads();

        uint32_t cur = sb + (uint32_t)(c % 3) * STAGE_BYTES;
        mma_pass32(cur, cur + TILE32_BYTES, acc, wm, wn, lane);

        __syncthreads();               // all warps done reading stage c%3
        if (c + 3 < 8) prefetch_chunk(sb, c + 3, m0, n0, tid);
    }

    // epilogue: per frag c0={g,2tg}, c1={g,2tg+1}, c2={g+8,2tg}, c3={g+8,2tg+1}
#pragma unroll
    for (int mf = 0; mf < 4; ++mf) {
#pragma unroll
        for (int nf = 0; nf < 8; ++nf) {
            int mrow = m0 + wm * 64 + mf * 16 + g;
            int col  = n0 + wn * 64 + nf * 8 + tg * 2;
            float* p = g_Y + (size_t)mrow * NCAT + col;
            *(float2*)p = make_float2(acc[mf][nf][0], acc[mf][nf][1]);
            *(float2*)(p + (size_t)8 * NCAT) = make_float2(acc[mf][nf][2], acc[mf][nf][3]);
        }
    }
}

// ---------------------------------------------------------------------------
// Combine: warp per row, 8 tags per thread, shuffle-only softmax.
// mode 0: q = unary*mask              -> softmax -> Ph
// mode 1: q = (unary*mask + msg)*mask -> softmax -> Ph
// mode 2: same q -> write to out (final)
// ---------------------------------------------------------------------------
__global__ void __launch_bounds__(256) combine_kernel(
    const float* __restrict__ unary_score,
    const float* __restrict__ mask,
    const float* __restrict__ start_t,   // [2,256]
    const float* __restrict__ end_t,     // [2,256]
    const int*   __restrict__ lengths,   // [32]
    float* __restrict__ out,
    int mode)
{
    int warp = threadIdx.x >> 5;
    int lane = threadIdx.x & 31;
    int row = blockIdx.x * 8 + warp;     // b*NS + s
    int b = row >> 10;
    int s = row & 1023;

    float m = mask[row];
    size_t base = (size_t)row * NT + lane;

    float q[8];
#pragma unroll
    for (int j = 0; j < 8; ++j) q[j] = unary_score[base + j * 32] * m;

    if (mode != 0) {
        float msg[8];
#pragma unroll
        for (int j = 0; j < 8; ++j) msg[j] = 0.0f;
        if (s >= 1) {
            const float* p = g_Y + (size_t)(row - 1) * NCAT + lane;
#pragma unroll
            for (int j = 0; j < 8; ++j) msg[j] += p[j * 32];
        }
        if (s >= 2) {
            const float* p = g_Y + (size_t)(row - 2) * NCAT + 256 + lane;
#pragma unroll
            for (int j = 0; j < 8; ++j) msg[j] += p[j * 32];
        }
        if (s <= NS - 2) {
            const float* p = g_Y + (size_t)(row + 1) * NCAT + 512 + lane;
#pragma unroll
            for (int j = 0; j < 8; ++j) msg[j] += p[j * 32];
        }
        if (s <= NS - 3) {
            const float* p = g_Y + (size_t)(row + 2) * NCAT + 768 + lane;
#pragma unroll
            for (int j = 0; j < 8; ++j) msg[j] += p[j * 32];
        }
        int len = __ldg(&lengths[b]);
        if (s == len - 1) {
#pragma unroll
            for (int j = 0; j < 8; ++j) msg[j] += end_t[lane + j * 32];
        }
        if (s == len - 2) {
#pragma unroll
            for (int j = 0; j < 8; ++j) msg[j] += end_t[256 + lane + j * 32];
        }
        if (s < 2) {
#pragma unroll
            for (int j = 0; j < 8; ++j) msg[j] += start_t[s * 256 + lane + j * 32];
        }
#pragma unroll
        for (int j = 0; j < 8; ++j) q[j] = (q[j] + msg[j]) * m;
    }

    if (mode == 2) {
#pragma unroll
        for (int j = 0; j < 8; ++j) out[base + j * 32] = q[j];
        return;
    }

    // softmax over 256 (8 per thread x 32 lanes), shuffle reductions only
    float mx = q[0];
#pragma unroll
    for (int j = 1; j < 8; ++j) mx = fmaxf(mx, q[j]);
#pragma unroll
    for (int o = 16; o; o >>= 1) mx = fmaxf(mx, __shfl_xor_sync(0xffffffffu, mx, o));

    float e[8];
    float sum = 0.0f;
#pragma unroll
    for (int j = 0; j < 8; ++j) { e[j] = __expf(q[j] - mx); sum += e[j]; }
#pragma unroll
    for (int o = 16; o; o >>= 1) sum += __shfl_xor_sync(0xffffffffu, sum, o);
    float rinv = __frcp_rn(sum);

#pragma unroll
    for (int j = 0; j < 8; ++j)
        g_Ph[base + j * 32] = __float2half_rn(e[j] * rinv);
}

// ---------------------------------------------------------------------------
// Input order: token_feats, unary_score, mask, transitions,
//              start_transitions, end_transitions, lengths
// ---------------------------------------------------------------------------
extern "C" void kernel_launch(void* const* d_in, const int* in_sizes, int n_in,
                              void* d_out, int out_size) {
    const float* unary   = (const float*)d_in[1];
    const float* mask    = (const float*)d_in[2];
    const float* trans   = (const float*)d_in[3];
    const float* start_t = (const float*)d_in[4];
    const float* end_t   = (const float*)d_in[5];
    const int*   lengths = (const int*)d_in[6];
    float* out = (float*)d_out;

    build_b_kernel<<<1024, 256>>>(trans);

    // initial P = softmax(unary * mask)
    combine_kernel<<<NBS / 8, 256>>>(unary, mask, start_t, end_t, lengths, out, 0);

    dim3 gemm_grid(NCAT / 128, NBS / 128);   // (8, 256)
    for (int it = 0; it < 3; ++it) {
        gemm_hmma_kernel<<<gemm_grid, 128, GEMM_SMEM>>>();
        int mode = (it == 2) ? 2 : 1;
        combine_kernel<<<NBS / 8, 256>>>(unary, mask, start_t, end_t, lengths, out, mode);
    }
}

// round 13
// speedup vs baseline: 2.2814x; 1.1347x over previous
#include <cuda_runtime.h>
#include <cuda_fp16.h>
#include <math.h>
#include <stdint.h>

// Problem constants
#define NB 32
#define NS 1024
#define NT 256
#define NBS 32768          // NB*NS rows
#define NCAT 1024          // 4*NT concatenated transition columns

// Static device scratch (allocation-free rule: __device__ globals)
__device__ __half g_Yh[(size_t)NBS * NCAT];  // P @ Tcat, fp16   67 MB (L2-resident)
__device__ __half g_Ph[NBS * NT];            // fp16 softmax(q)
__device__ __half g_BhT[NCAT * NT];          // B[n][k]  (K-major, i.e. B^T rows)

// ---------------------------------------------------------------------------
// Build B (K-major): Bcat[k][n] stored transposed as BT[n][k]
//   n in [0,256):    T0[k][n]          (left  j=1)
//   n in [256,512):  T1[k][n-256]      (left  j=2)
//   n in [512,768):  T0[n-512][k]      (right j=1)
//   n in [768,1024): T1[n-768][k]      (right j=2)
// ---------------------------------------------------------------------------
__global__ void build_b_kernel(const float* __restrict__ trans) {
    int idx = blockIdx.x * blockDim.x + threadIdx.x;   // 0 .. 262143
    int n = idx >> 8;          // 0..1023
    int k = idx & 255;         // 0..255
    float v;
    if (n < 256)       v = trans[k * 256 + n];
    else if (n < 512)  v = trans[65536 + k * 256 + (n - 256)];
    else if (n < 768)  v = trans[(n - 512) * 256 + k];
    else               v = trans[65536 + (n - 768) * 256 + k];
    g_BhT[n * NT + k] = __float2half_rn(v);
}

// ---------------------------------------------------------------------------
// HMMA GEMM: g_Yh[32768,1024] = Ph[32768,256] @ Bh^T   (fp16 out, fp32 accum)
// mma.sync.aligned.m16n8k16.row.col.f32.f16.f16.f32.
// Block 128x128, 128 threads = 4 warps (2m x 2n), warp tile 64x64.
// K in 8 chunks of 32 halves (64B rows). 3-stage cp.async pipeline:
// 3 stages x 2 tiles (A, B) x 8KB = 48KB smem.
// Swizzle: 16B unit at logical col c of row r lives at c ^ (((r>>1)&3)<<4).
// ---------------------------------------------------------------------------
#define TILE32_BYTES 8192                // 128 rows x 64 B
#define STAGE_BYTES  (2 * TILE32_BYTES)  // A, B
#define GEMM_SMEM    (3 * STAGE_BYTES)   // 48 KB

__device__ __forceinline__ void mma16816(float* d, uint32_t a0, uint32_t a1,
                                         uint32_t a2, uint32_t a3,
                                         uint32_t b0, uint32_t b1) {
    asm volatile(
        "mma.sync.aligned.m16n8k16.row.col.f32.f16.f16.f32 "
        "{%0,%1,%2,%3}, {%4,%5,%6,%7}, {%8,%9}, {%0,%1,%2,%3};"
        : "+f"(d[0]), "+f"(d[1]), "+f"(d[2]), "+f"(d[3])
        : "r"(a0), "r"(a1), "r"(a2), "r"(a3), "r"(b0), "r"(b1));
}

__device__ __forceinline__ void ldsm_x4(uint32_t addr, uint32_t& r0, uint32_t& r1,
                                        uint32_t& r2, uint32_t& r3) {
    asm volatile("ldmatrix.sync.aligned.m8n8.x4.shared.b16 {%0,%1,%2,%3}, [%4];"
                 : "=r"(r0), "=r"(r1), "=r"(r2), "=r"(r3) : "r"(addr));
}

__device__ __forceinline__ void cp16(uint32_t dst, const void* src) {
    asm volatile("cp.async.cg.shared.global [%0], [%1], 16;"
                 :: "r"(dst), "l"(src) : "memory");
}

__device__ __forceinline__ uint32_t sw32(uint32_t row) {   // 64B-row swizzle
    return ((row >> 1) & 3u) << 4;
}

// One pass over a 32-half K chunk. Warp tile 64x64: 4 m-frags x 8 n-frags,
// 2 k16 steps.
__device__ __forceinline__ void mma_pass32(uint32_t aB, uint32_t bB,
                                           float acc[4][8][4],
                                           int wm, int wn, int lane) {
    int lr = lane & 7;
    int quad = lane >> 3;              // 0..3: ldmatrix source-row group
    int rlow = (quad & 1) * 8 + lr;    // row within 16-row frag
    int khb = (quad >> 1) * 16;        // 0 or 16 bytes (k8 within k16)

#pragma unroll
    for (int ks = 0; ks < 2; ++ks) {
        uint32_t kb = (uint32_t)(ks * 32 + khb);
        uint32_t af[4][4];
#pragma unroll
        for (int mf = 0; mf < 4; ++mf) {
            uint32_t row = (uint32_t)(wm * 64 + mf * 16 + rlow);
            uint32_t addr = aB + row * 64 + (kb ^ sw32(row));
            ldsm_x4(addr, af[mf][0], af[mf][1], af[mf][2], af[mf][3]);
        }
        uint32_t bf[8][2];
#pragma unroll
        for (int i = 0; i < 4; ++i) {
            uint32_t row = (uint32_t)(wn * 64 + i * 16 + rlow);
            uint32_t addr = bB + row * 64 + (kb ^ sw32(row));
            ldsm_x4(addr, bf[2 * i][0], bf[2 * i + 1][0],
                    bf[2 * i][1], bf[2 * i + 1][1]);
        }
#pragma unroll
        for (int mf = 0; mf < 4; ++mf)
#pragma unroll
            for (int nf = 0; nf < 8; ++nf)
                mma16816(acc[mf][nf], af[mf][0], af[mf][1], af[mf][2],
                         af[mf][3], bf[nf][0], bf[nf][1]);
    }
}

// async-copy one 128-row x 64B tile gmem -> swizzled smem.
// thread t: rows t>>2 + 32p, 16B col (t&3)*16.
__device__ __forceinline__ void copy_tile32_async(uint32_t dst, const __half* srcBase,
                                                  int row0, int k0, int tid) {
    int r0 = tid >> 2;
    uint32_t col = (uint32_t)((tid & 3) * 16);
#pragma unroll
    for (int p = 0; p < 4; ++p) {
        int row = r0 + p * 32;
        const void* src = (const char*)(srcBase + (size_t)(row0 + row) * NT + k0) + col;
        cp16(dst + (uint32_t)(row * 64) + (col ^ sw32((uint32_t)row)), src);
    }
}

__device__ __forceinline__ void prefetch_chunk(uint32_t sb, int c,
                                               int m0, int n0, int tid) {
    uint32_t st = sb + (uint32_t)(c % 3) * STAGE_BYTES;
    int k0 = c * 32;
    copy_tile32_async(st,                g_Ph,  m0, k0, tid);
    copy_tile32_async(st + TILE32_BYTES, g_BhT, n0, k0, tid);
    asm volatile("cp.async.commit_group;" ::: "memory");
}

__global__ void __launch_bounds__(128, 2) gemm_hmma_kernel() {
    extern __shared__ char smem[];
    uint32_t sb = (uint32_t)__cvta_generic_to_shared(smem);

    int tid  = threadIdx.x;
    int wid  = tid >> 5;
    int lane = tid & 31;
    int wm = wid & 1;          // 0..1 : 64-row half
    int wn = wid >> 1;         // 0..1 : 64-col half
    int g  = lane >> 2;        // 0..7
    int tg = lane & 3;         // 0..3

    int m0 = blockIdx.y * 128;
    int n0 = blockIdx.x * 128;

    float acc[4][8][4];
#pragma unroll
    for (int i = 0; i < 4; i++)
#pragma unroll
        for (int j = 0; j < 8; j++)
#pragma unroll
            for (int r = 0; r < 4; r++) acc[i][j][r] = 0.0f;

    // prologue: prefetch chunks 0,1,2 into stages 0,1,2
    prefetch_chunk(sb, 0, m0, n0, tid);
    prefetch_chunk(sb, 1, m0, n0, tid);
    prefetch_chunk(sb, 2, m0, n0, tid);

    for (int c = 0; c < 8; ++c) {
        // wait until chunk c has landed (keep newest 2 groups in flight)
        if (c < 6)      asm volatile("cp.async.wait_group 2;" ::: "memory");
        else if (c == 6) asm volatile("cp.async.wait_group 1;" ::: "memory");
        else             asm volatile("cp.async.wait_group 0;" ::: "memory");
        __syncthreads();

        uint32_t cur = sb + (uint32_t)(c % 3) * STAGE_BYTES;
        mma_pass32(cur, cur + TILE32_BYTES, acc, wm, wn, lane);

        __syncthreads();               // all warps done reading stage c%3
        if (c + 3 < 8) prefetch_chunk(sb, c + 3, m0, n0, tid);
    }

    // epilogue (fp16): per frag rows {g, g+8}, cols {2tg, 2tg+1} -> half2
#pragma unroll
    for (int mf = 0; mf < 4; ++mf) {
#pragma unroll
        for (int nf = 0; nf < 8; ++nf) {
            int mrow = m0 + wm * 64 + mf * 16 + g;
            int col  = n0 + wn * 64 + nf * 8 + tg * 2;
            __half* p = g_Yh + (size_t)mrow * NCAT + col;
            *(__half2*)p = __floats2half2_rn(acc[mf][nf][0], acc[mf][nf][1]);
            *(__half2*)(p + (size_t)8 * NCAT) =
                __floats2half2_rn(acc[mf][nf][2], acc[mf][nf][3]);
        }
    }
}

// ---------------------------------------------------------------------------
// Combine: warp per row, 8 tags per thread, shuffle-only softmax.
// mode 0: q = unary*mask              -> softmax -> Ph
// mode 1: q = (unary*mask + msg)*mask -> softmax -> Ph
// mode 2: same q -> write to out (final)
// ---------------------------------------------------------------------------
__global__ void __launch_bounds__(256) combine_kernel(
    const float* __restrict__ unary_score,
    const float* __restrict__ mask,
    const float* __restrict__ start_t,   // [2,256]
    const float* __restrict__ end_t,     // [2,256]
    const int*   __restrict__ lengths,   // [32]
    float* __restrict__ out,
    int mode)
{
    int warp = threadIdx.x >> 5;
    int lane = threadIdx.x & 31;
    int row = blockIdx.x * 8 + warp;     // b*NS + s
    int b = row >> 10;
    int s = row & 1023;

    float m = mask[row];
    size_t base = (size_t)row * NT + lane;

    float q[8];
#pragma unroll
    for (int j = 0; j < 8; ++j) q[j] = unary_score[base + j * 32] * m;

    if (mode != 0) {
        float msg[8];
#pragma unroll
        for (int j = 0; j < 8; ++j) msg[j] = 0.0f;
        if (s >= 1) {
            const __half* p = g_Yh + (size_t)(row - 1) * NCAT + lane;
#pragma unroll
            for (int j = 0; j < 8; ++j) msg[j] += __half2float(p[j * 32]);
        }
        if (s >= 2) {
            const __half* p = g_Yh + (size_t)(row - 2) * NCAT + 256 + lane;
#pragma unroll
            for (int j = 0; j < 8; ++j) msg[j] += __half2float(p[j * 32]);
        }
        if (s <= NS - 2) {
            const __half* p = g_Yh + (size_t)(row + 1) * NCAT + 512 + lane;
#pragma unroll
            for (int j = 0; j < 8; ++j) msg[j] += __half2float(p[j * 32]);
        }
        if (s <= NS - 3) {
            const __half* p = g_Yh + (size_t)(row + 2) * NCAT + 768 + lane;
#pragma unroll
            for (int j = 0; j < 8; ++j) msg[j] += __half2float(p[j * 32]);
        }
        int len = __ldg(&lengths[b]);
        if (s == len - 1) {
#pragma unroll
            for (int j = 0; j < 8; ++j) msg[j] += end_t[lane + j * 32];
        }
        if (s == len - 2) {
#pragma unroll
            for (int j = 0; j < 8; ++j) msg[j] += end_t[256 + lane + j * 32];
        }
        if (s < 2) {
#pragma unroll
            for (int j = 0; j < 8; ++j) msg[j] += start_t[s * 256 + lane + j * 32];
        }
#pragma unroll
        for (int j = 0; j < 8; ++j) q[j] = (q[j] + msg[j]) * m;
    }

    if (mode == 2) {
#pragma unroll
        for (int j = 0; j < 8; ++j) out[base + j * 32] = q[j];
        return;
    }

    // softmax over 256 (8 per thread x 32 lanes), shuffle reductions only
    float mx = q[0];
#pragma unroll
    for (int j = 1; j < 8; ++j) mx = fmaxf(mx, q[j]);
#pragma unroll
    for (int o = 16; o; o >>= 1) mx = fmaxf(mx, __shfl_xor_sync(0xffffffffu, mx, o));

    float e[8];
    float sum = 0.0f;
#pragma unroll
    for (int j = 0; j < 8; ++j) { e[j] = __expf(q[j] - mx); sum += e[j]; }
#pragma unroll
    for (int o = 16; o; o >>= 1) sum += __shfl_xor_sync(0xffffffffu, sum, o);
    float rinv = __frcp_rn(sum);

#pragma unroll
    for (int j = 0; j < 8; ++j)
        g_Ph[base + j * 32] = __float2half_rn(e[j] * rinv);
}

// ---------------------------------------------------------------------------
// Input order: token_feats, unary_score, mask, transitions,
//              start_transitions, end_transitions, lengths
// ---------------------------------------------------------------------------
extern "C" void kernel_launch(void* const* d_in, const int* in_sizes, int n_in,
                              void* d_out, int out_size) {
    const float* unary   = (const float*)d_in[1];
    const float* mask    = (const float*)d_in[2];
    const float* trans   = (const float*)d_in[3];
    const float* start_t = (const float*)d_in[4];
    const float* end_t   = (const float*)d_in[5];
    const int*   lengths = (const int*)d_in[6];
    float* out = (float*)d_out;

    build_b_kernel<<<1024, 256>>>(trans);

    // initial P = softmax(unary * mask)
    combine_kernel<<<NBS / 8, 256>>>(unary, mask, start_t, end_t, lengths, out, 0);

    dim3 gemm_grid(NCAT / 128, NBS / 128);   // (8, 256)
    for (int it = 0; it < 3; ++it) {
        gemm_hmma_kernel<<<gemm_grid, 128, GEMM_SMEM>>>();
        int mode = (it == 2) ? 2 : 1;
        combine_kernel<<<NBS / 8, 256>>>(unary, mask, start_t, end_t, lengths, out, mode);
    }
}

// round 14
// speedup vs baseline: 2.6003x; 1.1398x over previous
#include <cuda_runtime.h>
#include <cuda_fp16.h>
#include <math.h>
#include <stdint.h>

// Problem constants
#define NB 32
#define NS 1024
#define NT 256
#define NBS 32768          // NB*NS rows
#define KCAT 1024          // 4*NT concatenated K (shift segments)

// Static device scratch (allocation-free rule: __device__ globals)
__device__ __half g_Mh[(size_t)NBS * NT];    // msg = Acat @ Bcat2, fp16  16.8 MB
__device__ __half g_Ph[NBS * NT];            // fp16 softmax(q)           16.8 MB
__device__ __half g_BT[NT * KCAT];           // Bcat2^T[n][k], K-major    0.5 MB

__constant__ int c_shift[4] = {-1, -2, 1, 2};

// ---------------------------------------------------------------------------
// Build Bcat2^T (K-major rows): BT[n][k], n in [0,256), k in [0,1024)
// segment j = k>>8, kk = k&255:
//   j=0: T0[kk][n]   (msg from P[s-1])
//   j=1: T1[kk][n]   (msg from P[s-2])
//   j=2: T0[n][kk]   (msg from P[s+1])
//   j=3: T1[n][kk]   (msg from P[s+2])
// transitions layout: [2, 256, 256] row-major
// ---------------------------------------------------------------------------
__global__ void build_b_kernel(const float* __restrict__ trans) {
    int idx = blockIdx.x * blockDim.x + threadIdx.x;   // 0 .. 262143
    int n = idx >> 10;         // 0..255
    int k = idx & 1023;        // 0..1023
    int seg = k >> 8;
    int kk = k & 255;
    float v;
    if (seg == 0)      v = trans[kk * 256 + n];
    else if (seg == 1) v = trans[65536 + kk * 256 + n];
    else if (seg == 2) v = trans[n * 256 + kk];
    else               v = trans[65536 + n * 256 + kk];
    g_BT[n * KCAT + k] = __float2half_rn(v);
}

// ---------------------------------------------------------------------------
// HMMA GEMM: g_Mh[32768,256] = Acat[32768,1024] @ Bcat2  (fp16 out, fp32 acc)
// Acat[row][k] = P[row + shift(k>>8)][k&255], zero when s+shift out of [0,NS).
// mma.sync.aligned.m16n8k16.row.col.f32.f16.f16.f32.
// Block 128x128, 128 threads = 4 warps (2m x 2n), warp tile 64x64.
// K in 32 chunks of 32 halves (64B rows). 3-stage cp.async pipeline (48KB).
// Swizzle: 16B unit at logical col c of row r lives at c ^ (((r>>1)&3)<<4).
// ---------------------------------------------------------------------------
#define TILE32_BYTES 8192                // 128 rows x 64 B
#define STAGE_BYTES  (2 * TILE32_BYTES)  // A, B
#define GEMM_SMEM    (3 * STAGE_BYTES)   // 48 KB
#define NCHUNK 32

__device__ __forceinline__ void mma16816(float* d, uint32_t a0, uint32_t a1,
                                         uint32_t a2, uint32_t a3,
                                         uint32_t b0, uint32_t b1) {
    asm volatile(
        "mma.sync.aligned.m16n8k16.row.col.f32.f16.f16.f32 "
        "{%0,%1,%2,%3}, {%4,%5,%6,%7}, {%8,%9}, {%0,%1,%2,%3};"
        : "+f"(d[0]), "+f"(d[1]), "+f"(d[2]), "+f"(d[3])
        : "r"(a0), "r"(a1), "r"(a2), "r"(a3), "r"(b0), "r"(b1));
}

__device__ __forceinline__ void ldsm_x4(uint32_t addr, uint32_t& r0, uint32_t& r1,
                                        uint32_t& r2, uint32_t& r3) {
    asm volatile("ldmatrix.sync.aligned.m8n8.x4.shared.b16 {%0,%1,%2,%3}, [%4];"
                 : "=r"(r0), "=r"(r1), "=r"(r2), "=r"(r3) : "r"(addr));
}

// cp.async with src-size: bytes beyond srcsz are zero-filled (srcsz=0 -> zeros)
__device__ __forceinline__ void cp16z(uint32_t dst, const void* src, uint32_t srcsz) {
    asm volatile("cp.async.cg.shared.global [%0], [%1], 16, %2;"
                 :: "r"(dst), "l"(src), "r"(srcsz) : "memory");
}

__device__ __forceinline__ uint32_t sw32(uint32_t row) {   // 64B-row swizzle
    return ((row >> 1) & 3u) << 4;
}

// One pass over a 32-half K chunk. Warp tile 64x64: 4 m-frags x 8 n-frags,
// 2 k16 steps.
__device__ __forceinline__ void mma_pass32(uint32_t aB, uint32_t bB,
                                           float acc[4][8][4],
                                           int wm, int wn, int lane) {
    int lr = lane & 7;
    int quad = lane >> 3;              // 0..3: ldmatrix source-row group
    int rlow = (quad & 1) * 8 + lr;    // row within 16-row frag
    int khb = (quad >> 1) * 16;        // 0 or 16 bytes (k8 within k16)

#pragma unroll
    for (int ks = 0; ks < 2; ++ks) {
        uint32_t kb = (uint32_t)(ks * 32 + khb);
        uint32_t af[4][4];
#pragma unroll
        for (int mf = 0; mf < 4; ++mf) {
            uint32_t row = (uint32_t)(wm * 64 + mf * 16 + rlow);
            uint32_t addr = aB + row * 64 + (kb ^ sw32(row));
            ldsm_x4(addr, af[mf][0], af[mf][1], af[mf][2], af[mf][3]);
        }
        uint32_t bf[8][2];
#pragma unroll
        for (int i = 0; i < 4; ++i) {
            uint32_t row = (uint32_t)(wn * 64 + i * 16 + rlow);
            uint32_t addr = bB + row * 64 + (kb ^ sw32(row));
            ldsm_x4(addr, bf[2 * i][0], bf[2 * i + 1][0],
                    bf[2 * i][1], bf[2 * i + 1][1]);
        }
#pragma unroll
        for (int mf = 0; mf < 4; ++mf)
#pragma unroll
            for (int nf = 0; nf < 8; ++nf)
                mma16816(acc[mf][nf], af[mf][0], af[mf][1], af[mf][2],
                         af[mf][3], bf[nf][0], bf[nf][1]);
    }
}

// A-tile: 128 rows x 64B from shifted P. chunk c -> seg = (c*32)>>8,
// column kk0 = (c*32)&255 within P row. Out-of-range rows zero-filled.
__device__ __forceinline__ void copy_tileA_async(uint32_t dst, int m0, int c, int tid) {
    int k0 = c * 32;
    int seg = k0 >> 8;
    int kk0 = k0 & 255;
    int shift = c_shift[seg];
    int r0 = tid >> 2;
    uint32_t col = (uint32_t)((tid & 3) * 16);
#pragma unroll
    for (int p = 0; p < 4; ++p) {
        int row = r0 + p * 32;
        int gr = m0 + row;
        int s = gr & (NS - 1);
        uint32_t ok = ((unsigned)(s + shift) < (unsigned)NS) ? 16u : 0u;
        const __half* sp = ok ? (g_Ph + (size_t)(gr + shift) * NT + kk0) : g_Ph;
        cp16z(dst + (uint32_t)(row * 64) + (col ^ sw32((uint32_t)row)),
              (const char*)sp + col, ok);
    }
}

// B-tile: 128 rows x 64B from g_BT (rows n0..n0+127, byte offset 2*k0)
__device__ __forceinline__ void copy_tileB_async(uint32_t dst, int n0, int c, int tid) {
    int k0 = c * 32;
    int r0 = tid >> 2;
    uint32_t col = (uint32_t)((tid & 3) * 16);
#pragma unroll
    for (int p = 0; p < 4; ++p) {
        int row = r0 + p * 32;
        const void* src = (const char*)(g_BT + (size_t)(n0 + row) * KCAT + k0) + col;
        cp16z(dst + (uint32_t)(row * 64) + (col ^ sw32((uint32_t)row)), src, 16u);
    }
}

__device__ __forceinline__ void prefetch_chunk(uint32_t sb, int c,
                                               int m0, int n0, int tid) {
    uint32_t st = sb + (uint32_t)(c % 3) * STAGE_BYTES;
    copy_tileA_async(st, m0, c, tid);
    copy_tileB_async(st + TILE32_BYTES, n0, c, tid);
    asm volatile("cp.async.commit_group;" ::: "memory");
}

__global__ void __launch_bounds__(128, 2) gemm_hmma_kernel() {
    extern __shared__ char smem[];
    uint32_t sb = (uint32_t)__cvta_generic_to_shared(smem);

    int tid  = threadIdx.x;
    int wid  = tid >> 5;
    int lane = tid & 31;
    int wm = wid & 1;          // 0..1 : 64-row half
    int wn = wid >> 1;         // 0..1 : 64-col half
    int g  = lane >> 2;        // 0..7
    int tg = lane & 3;         // 0..3

    int m0 = blockIdx.y * 128;
    int n0 = blockIdx.x * 128;

    float acc[4][8][4];
#pragma unroll
    for (int i = 0; i < 4; i++)
#pragma unroll
        for (int j = 0; j < 8; j++)
#pragma unroll
            for (int r = 0; r < 4; r++) acc[i][j][r] = 0.0f;

    // prologue: prefetch chunks 0,1,2 into stages 0,1,2
    prefetch_chunk(sb, 0, m0, n0, tid);
    prefetch_chunk(sb, 1, m0, n0, tid);
    prefetch_chunk(sb, 2, m0, n0, tid);

    for (int c = 0; c < NCHUNK; ++c) {
        if (c < NCHUNK - 2)       asm volatile("cp.async.wait_group 2;" ::: "memory");
        else if (c == NCHUNK - 2) asm volatile("cp.async.wait_group 1;" ::: "memory");
        else                      asm volatile("cp.async.wait_group 0;" ::: "memory");
        __syncthreads();

        uint32_t cur = sb + (uint32_t)(c % 3) * STAGE_BYTES;
        mma_pass32(cur, cur + TILE32_BYTES, acc, wm, wn, lane);

        __syncthreads();               // all warps done reading stage c%3
        if (c + 3 < NCHUNK) prefetch_chunk(sb, c + 3, m0, n0, tid);
    }

    // epilogue (fp16): per frag rows {g, g+8}, cols {2tg, 2tg+1} -> half2
#pragma unroll
    for (int mf = 0; mf < 4; ++mf) {
#pragma unroll
        for (int nf = 0; nf < 8; ++nf) {
            int mrow = m0 + wm * 64 + mf * 16 + g;
            int col  = n0 + wn * 64 + nf * 8 + tg * 2;
            __half* p = g_Mh + (size_t)mrow * NT + col;
            *(__half2*)p = __floats2half2_rn(acc[mf][nf][0], acc[mf][nf][1]);
            *(__half2*)(p + (size_t)8 * NT) =
                __floats2half2_rn(acc[mf][nf][2], acc[mf][nf][3]);
        }
    }
}

// ---------------------------------------------------------------------------
// Combine: warp per row, 8 tags per thread, shuffle-only softmax.
// mode 0: q = unary*mask                      -> softmax -> Ph
// mode 1: q = (unary*mask + msg + bnd)*mask   -> softmax -> Ph
// mode 2: same q -> write to out (final)
// ---------------------------------------------------------------------------
__global__ void __launch_bounds__(256) combine_kernel(
    const float* __restrict__ unary_score,
    const float* __restrict__ mask,
    const float* __restrict__ start_t,   // [2,256]
    const float* __restrict__ end_t,     // [2,256]
    const int*   __restrict__ lengths,   // [32]
    float* __restrict__ out,
    int mode)
{
    int warp = threadIdx.x >> 5;
    int lane = threadIdx.x & 31;
    int row = blockIdx.x * 8 + warp;     // b*NS + s
    int b = row >> 10;
    int s = row & 1023;

    float m = mask[row];
    size_t base = (size_t)row * NT + lane;

    float q[8];
#pragma unroll
    for (int j = 0; j < 8; ++j) q[j] = unary_score[base + j * 32] * m;

    if (mode != 0) {
        float msg[8];
        const __half* p = g_Mh + base;
#pragma unroll
        for (int j = 0; j < 8; ++j) msg[j] = __half2float(p[j * 32]);

        int len = __ldg(&lengths[b]);
        if (s == len - 1) {
#pragma unroll
            for (int j = 0; j < 8; ++j) msg[j] += end_t[lane + j * 32];
        }
        if (s == len - 2) {
#pragma unroll
            for (int j = 0; j < 8; ++j) msg[j] += end_t[256 + lane + j * 32];
        }
        if (s < 2) {
#pragma unroll
            for (int j = 0; j < 8; ++j) msg[j] += start_t[s * 256 + lane + j * 32];
        }
#pragma unroll
        for (int j = 0; j < 8; ++j) q[j] = (q[j] + msg[j]) * m;
    }

    if (mode == 2) {
#pragma unroll
        for (int j = 0; j < 8; ++j) out[base + j * 32] = q[j];
        return;
    }

    // softmax over 256 (8 per thread x 32 lanes), shuffle reductions only
    float mx = q[0];
#pragma unroll
    for (int j = 1; j < 8; ++j) mx = fmaxf(mx, q[j]);
#pragma unroll
    for (int o = 16; o; o >>= 1) mx = fmaxf(mx, __shfl_xor_sync(0xffffffffu, mx, o));

    float e[8];
    float sum = 0.0f;
#pragma unroll
    for (int j = 0; j < 8; ++j) { e[j] = __expf(q[j] - mx); sum += e[j]; }
#pragma unroll
    for (int o = 16; o; o >>= 1) sum += __shfl_xor_sync(0xffffffffu, sum, o);
    float rinv = __frcp_rn(sum);

#pragma unroll
    for (int j = 0; j < 8; ++j)
        g_Ph[base + j * 32] = __float2half_rn(e[j] * rinv);
}

// ---------------------------------------------------------------------------
// Input order: token_feats, unary_score, mask, transitions,
//              start_transitions, end_transitions, lengths
// ---------------------------------------------------------------------------
extern "C" void kernel_launch(void* const* d_in, const int* in_sizes, int n_in,
                              void* d_out, int out_size) {
    const float* unary   = (const float*)d_in[1];
    const float* mask    = (const float*)d_in[2];
    const float* trans   = (const float*)d_in[3];
    const float* start_t = (const float*)d_in[4];
    const float* end_t   = (const float*)d_in[5];
    const int*   lengths = (const int*)d_in[6];
    float* out = (float*)d_out;

    build_b_kernel<<<1024, 256>>>(trans);

    // initial P = softmax(unary * mask)
    combine_kernel<<<NBS / 8, 256>>>(unary, mask, start_t, end_t, lengths, out, 0);

    dim3 gemm_grid(NT / 128, NBS / 128);     // (2, 256) = 512 CTAs
    for (int it = 0; it < 3; ++it) {
        gemm_hmma_kernel<<<gemm_grid, 128, GEMM_SMEM>>>();
        int mode = (it == 2) ? 2 : 1;
        combine_kernel<<<NBS / 8, 256>>>(unary, mask, start_t, end_t, lengths, out, mode);
    }
}

// round 15
// speedup vs baseline: 3.1036x; 1.1936x over previous
#include <cuda_runtime.h>
#include <cuda_fp16.h>
#include <math.h>
#include <stdint.h>

// Problem constants
#define NB 32
#define NS 1024
#define NT 256
#define NBS 32768          // NB*NS rows
#define KCAT 1024          // 4*NT concatenated K (shift segments)

// Static device scratch (allocation-free rule: __device__ globals; zero-init)
__device__ __half g_Mh[(size_t)NBS * NT];    // msg = Acat @ Bcat2, fp16  16.8 MB
__device__ __half g_Ph[NBS * NT];            // fp16 softmax(q)           16.8 MB
__device__ __half g_BT[NT * KCAT];           // Bcat2^T[n][k], K-major    0.5 MB

__constant__ int c_shift[4] = {-1, -2, 1, 2};

// ---------------------------------------------------------------------------
// Build Bcat2^T (K-major rows): BT[n][k], n in [0,256), k in [0,1024)
// segment j = k>>8, kk = k&255:
//   j=0: T0[kk][n]   (msg from P[s-1])
//   j=1: T1[kk][n]   (msg from P[s-2])
//   j=2: T0[n][kk]   (msg from P[s+1])
//   j=3: T1[n][kk]   (msg from P[s+2])
// transitions layout: [2, 256, 256] row-major
// ---------------------------------------------------------------------------
__global__ void build_b_kernel(const float* __restrict__ trans) {
    int idx = blockIdx.x * blockDim.x + threadIdx.x;   // 0 .. 262143
    int n = idx >> 10;         // 0..255
    int k = idx & 1023;        // 0..1023
    int seg = k >> 8;
    int kk = k & 255;
    float v;
    if (seg == 0)      v = trans[kk * 256 + n];
    else if (seg == 1) v = trans[65536 + kk * 256 + n];
    else if (seg == 2) v = trans[n * 256 + kk];
    else               v = trans[65536 + n * 256 + kk];
    g_BT[n * KCAT + k] = __float2half_rn(v);
}

// ---------------------------------------------------------------------------
// HMMA GEMM: g_Mh[32768,256] = Acat[32768,1024] @ Bcat2  (fp16 out, fp32 acc)
// Acat[row][k] = P[row + shift(k>>8)][k&255], zero when s+shift out of [0,NS).
// Block 128x128, 128 threads = 4 warps (2m x 2n), warp tile 64x64.
// K in 32 chunks of 32 halves (64B rows). 3-stage cp.async pipeline, ONE
// barrier per chunk. CTAs whose whole M-tile is masked (s0 >= len) exit
// immediately: their receivers have mask=0, so msg never matters.
// Swizzle: 16B unit at logical col c of row r lives at c ^ (((r>>1)&3)<<4).
// ---------------------------------------------------------------------------
#define TILE32_BYTES 8192                // 128 rows x 64 B
#define STAGE_BYTES  (2 * TILE32_BYTES)  // A, B
#define GEMM_SMEM    (3 * STAGE_BYTES)   // 48 KB
#define NCHUNK 32

__device__ __forceinline__ void mma16816(float* d, uint32_t a0, uint32_t a1,
                                         uint32_t a2, uint32_t a3,
                                         uint32_t b0, uint32_t b1) {
    asm volatile(
        "mma.sync.aligned.m16n8k16.row.col.f32.f16.f16.f32 "
        "{%0,%1,%2,%3}, {%4,%5,%6,%7}, {%8,%9}, {%0,%1,%2,%3};"
        : "+f"(d[0]), "+f"(d[1]), "+f"(d[2]), "+f"(d[3])
        : "r"(a0), "r"(a1), "r"(a2), "r"(a3), "r"(b0), "r"(b1));
}

__device__ __forceinline__ void ldsm_x4(uint32_t addr, uint32_t& r0, uint32_t& r1,
                                        uint32_t& r2, uint32_t& r3) {
    asm volatile("ldmatrix.sync.aligned.m8n8.x4.shared.b16 {%0,%1,%2,%3}, [%4];"
                 : "=r"(r0), "=r"(r1), "=r"(r2), "=r"(r3) : "r"(addr));
}

// cp.async with src-size: bytes beyond srcsz are zero-filled (srcsz=0 -> zeros)
__device__ __forceinline__ void cp16z(uint32_t dst, const void* src, uint32_t srcsz) {
    asm volatile("cp.async.cg.shared.global [%0], [%1], 16, %2;"
                 :: "r"(dst), "l"(src), "r"(srcsz) : "memory");
}

__device__ __forceinline__ uint32_t sw32(uint32_t row) {   // 64B-row swizzle
    return ((row >> 1) & 3u) << 4;
}

// One pass over a 32-half K chunk. Warp tile 64x64: 4 m-frags x 8 n-frags,
// 2 k16 steps.
__device__ __forceinline__ void mma_pass32(uint32_t aB, uint32_t bB,
                                           float acc[4][8][4],
                                           int wm, int wn, int lane) {
    int lr = lane & 7;
    int quad = lane >> 3;              // 0..3: ldmatrix source-row group
    int rlow = (quad & 1) * 8 + lr;    // row within 16-row frag
    int khb = (quad >> 1) * 16;        // 0 or 16 bytes (k8 within k16)

#pragma unroll
    for (int ks = 0; ks < 2; ++ks) {
        uint32_t kb = (uint32_t)(ks * 32 + khb);
        uint32_t af[4][4];
#pragma unroll
        for (int mf = 0; mf < 4; ++mf) {
            uint32_t row = (uint32_t)(wm * 64 + mf * 16 + rlow);
            uint32_t addr = aB + row * 64 + (kb ^ sw32(row));
            ldsm_x4(addr, af[mf][0], af[mf][1], af[mf][2], af[mf][3]);
        }
        uint32_t bf[8][2];
#pragma unroll
        for (int i = 0; i < 4; ++i) {
            uint32_t row = (uint32_t)(wn * 64 + i * 16 + rlow);
            uint32_t addr = bB + row * 64 + (kb ^ sw32(row));
            ldsm_x4(addr, bf[2 * i][0], bf[2 * i + 1][0],
                    bf[2 * i][1], bf[2 * i + 1][1]);
        }
#pragma unroll
        for (int mf = 0; mf < 4; ++mf)
#pragma unroll
            for (int nf = 0; nf < 8; ++nf)
                mma16816(acc[mf][nf], af[mf][0], af[mf][1], af[mf][2],
                         af[mf][3], bf[nf][0], bf[nf][1]);
    }
}

// A-tile: 128 rows x 64B from shifted P. chunk c -> seg = (c*32)>>8,
// column kk0 = (c*32)&255 within P row. Out-of-range rows zero-filled.
__device__ __forceinline__ void copy_tileA_async(uint32_t dst, int m0, int c, int tid) {
    int k0 = c * 32;
    int seg = k0 >> 8;
    int kk0 = k0 & 255;
    int shift = c_shift[seg];
    int r0 = tid >> 2;
    uint32_t col = (uint32_t)((tid & 3) * 16);
#pragma unroll
    for (int p = 0; p < 4; ++p) {
        int row = r0 + p * 32;
        int gr = m0 + row;
        int s = gr & (NS - 1);
        uint32_t ok = ((unsigned)(s + shift) < (unsigned)NS) ? 16u : 0u;
        const __half* sp = ok ? (g_Ph + (size_t)(gr + shift) * NT + kk0) : g_Ph;
        cp16z(dst + (uint32_t)(row * 64) + (col ^ sw32((uint32_t)row)),
              (const char*)sp + col, ok);
    }
}

// B-tile: 128 rows x 64B from g_BT (rows n0..n0+127, byte offset 2*k0)
__device__ __forceinline__ void copy_tileB_async(uint32_t dst, int n0, int c, int tid) {
    int k0 = c * 32;
    int r0 = tid >> 2;
    uint32_t col = (uint32_t)((tid & 3) * 16);
#pragma unroll
    for (int p = 0; p < 4; ++p) {
        int row = r0 + p * 32;
        const void* src = (const char*)(g_BT + (size_t)(n0 + row) * KCAT + k0) + col;
        cp16z(dst + (uint32_t)(row * 64) + (col ^ sw32((uint32_t)row)), src, 16u);
    }
}

__device__ __forceinline__ void prefetch_chunk(uint32_t sb, int c,
                                               int m0, int n0, int tid) {
    uint32_t st = sb + (uint32_t)(c % 3) * STAGE_BYTES;
    copy_tileA_async(st, m0, c, tid);
    copy_tileB_async(st + TILE32_BYTES, n0, c, tid);
    asm volatile("cp.async.commit_group;" ::: "memory");
}

__global__ void __launch_bounds__(128, 2) gemm_hmma_kernel(
    const int* __restrict__ lengths)
{
    extern __shared__ char smem[];
    uint32_t sb = (uint32_t)__cvta_generic_to_shared(smem);

    int m0 = blockIdx.y * 128;
    int n0 = blockIdx.x * 128;

    // All 128 receiver rows of this tile lie in one sequence (1024 % 128 == 0).
    // If they are all masked (s0 >= len), their q is zeroed in combine no
    // matter what msg holds -> skip the whole tile (stale g_Mh is finite).
    int s0 = m0 & (NS - 1);
    int b  = m0 >> 10;
    if (s0 >= __ldg(&lengths[b])) return;

    int tid  = threadIdx.x;
    int wid  = tid >> 5;
    int lane = tid & 31;
    int wm = wid & 1;          // 0..1 : 64-row half
    int wn = wid >> 1;         // 0..1 : 64-col half
    int g  = lane >> 2;        // 0..7
    int tg = lane & 3;         // 0..3

    float acc[4][8][4];
#pragma unroll
    for (int i = 0; i < 4; i++)
#pragma unroll
        for (int j = 0; j < 8; j++)
#pragma unroll
            for (int r = 0; r < 4; r++) acc[i][j][r] = 0.0f;

    // prologue: prefetch chunks 0,1 (depth 2, 3 stages)
    prefetch_chunk(sb, 0, m0, n0, tid);
    prefetch_chunk(sb, 1, m0, n0, tid);

    for (int c = 0; c < NCHUNK; ++c) {
        // chunk c landed when <=1 newer group still pending
        if (c + 1 < NCHUNK) asm volatile("cp.async.wait_group 1;" ::: "memory");
        else                asm volatile("cp.async.wait_group 0;" ::: "memory");
        __syncthreads();
        // This barrier also proves every warp finished chunk c-1, so its
        // stage ((c+2)%3) is safe to refill now.
        if (c + 2 < NCHUNK) prefetch_chunk(sb, c + 2, m0, n0, tid);

        uint32_t cur = sb + (uint32_t)(c % 3) * STAGE_BYTES;
        mma_pass32(cur, cur + TILE32_BYTES, acc, wm, wn, lane);
    }

    // epilogue (fp16): per frag rows {g, g+8}, cols {2tg, 2tg+1} -> half2
#pragma unroll
    for (int mf = 0; mf < 4; ++mf) {
#pragma unroll
        for (int nf = 0; nf < 8; ++nf) {
            int mrow = m0 + wm * 64 + mf * 16 + g;
            int col  = n0 + wn * 64 + nf * 8 + tg * 2;
            __half* p = g_Mh + (size_t)mrow * NT + col;
            *(__half2*)p = __floats2half2_rn(acc[mf][nf][0], acc[mf][nf][1]);
            *(__half2*)(p + (size_t)8 * NT) =
                __floats2half2_rn(acc[mf][nf][2], acc[mf][nf][3]);
        }
    }
}

// ---------------------------------------------------------------------------
// Combine: warp per row, 8 tags per thread, shuffle-only softmax.
// mode 0: q = unary*mask                      -> softmax -> Ph
// mode 1: q = (unary*mask + msg + bnd)*mask   -> softmax -> Ph
// mode 2: same q -> write to out (final)
// ---------------------------------------------------------------------------
__global__ void __launch_bounds__(256) combine_kernel(
    const float* __restrict__ unary_score,
    const float* __restrict__ mask,
    const float* __restrict__ start_t,   // [2,256]
    const float* __restrict__ end_t,     // [2,256]
    const int*   __restrict__ lengths,   // [32]
    float* __restrict__ out,
    int mode)
{
    int warp = threadIdx.x >> 5;
    int lane = threadIdx.x & 31;
    int row = blockIdx.x * 8 + warp;     // b*NS + s
    int b = row >> 10;
    int s = row & 1023;

    float m = mask[row];
    size_t base = (size_t)row * NT + lane;

    float q[8];
#pragma unroll
    for (int j = 0; j < 8; ++j) q[j] = unary_score[base + j * 32] * m;

    if (mode != 0) {
        float msg[8];
        const __half* p = g_Mh + base;
#pragma unroll
        for (int j = 0; j < 8; ++j) msg[j] = __half2float(p[j * 32]);

        int len = __ldg(&lengths[b]);
        if (s == len - 1) {
#pragma unroll
            for (int j = 0; j < 8; ++j) msg[j] += end_t[lane + j * 32];
        }
        if (s == len - 2) {
#pragma unroll
            for (int j = 0; j < 8; ++j) msg[j] += end_t[256 + lane + j * 32];
        }
        if (s < 2) {
#pragma unroll
            for (int j = 0; j < 8; ++j) msg[j] += start_t[s * 256 + lane + j * 32];
        }
#pragma unroll
        for (int j = 0; j < 8; ++j) q[j] = (q[j] + msg[j]) * m;
    }

    if (mode == 2) {
#pragma unroll
        for (int j = 0; j < 8; ++j) out[base + j * 32] = q[j];
        return;
    }

    // softmax over 256 (8 per thread x 32 lanes), shuffle reductions only
    float mx = q[0];
#pragma unroll
    for (int j = 1; j < 8; ++j) mx = fmaxf(mx, q[j]);
#pragma unroll
    for (int o = 16; o; o >>= 1) mx = fmaxf(mx, __shfl_xor_sync(0xffffffffu, mx, o));

    float e[8];
    float sum = 0.0f;
#pragma unroll
    for (int j = 0; j < 8; ++j) { e[j] = __expf(q[j] - mx); sum += e[j]; }
#pragma unroll
    for (int o = 16; o; o >>= 1) sum += __shfl_xor_sync(0xffffffffu, sum, o);
    float rinv = __frcp_rn(sum);

#pragma unroll
    for (int j = 0; j < 8; ++j)
        g_Ph[base + j * 32] = __float2half_rn(e[j] * rinv);
}

// ---------------------------------------------------------------------------
// Input order: token_feats, unary_score, mask, transitions,
//              start_transitions, end_transitions, lengths
// ---------------------------------------------------------------------------
extern "C" void kernel_launch(void* const* d_in, const int* in_sizes, int n_in,
                              void* d_out, int out_size) {
    const float* unary   = (const float*)d_in[1];
    const float* mask    = (const float*)d_in[2];
    const float* trans   = (const float*)d_in[3];
    const float* start_t = (const float*)d_in[4];
    const float* end_t   = (const float*)d_in[5];
    const int*   lengths = (const int*)d_in[6];
    float* out = (float*)d_out;

    build_b_kernel<<<1024, 256>>>(trans);

    // initial P = softmax(unary * mask)
    combine_kernel<<<NBS / 8, 256>>>(unary, mask, start_t, end_t, lengths, out, 0);

    dim3 gemm_grid(NT / 128, NBS / 128);     // (2, 256) = 512 CTAs
    for (int it = 0; it < 3; ++it) {
        gemm_hmma_kernel<<<gemm_grid, 128, GEMM_SMEM>>>(lengths);
        int mode = (it == 2) ? 2 : 1;
        combine_kernel<<<NBS / 8, 256>>>(unary, mask, start_t, end_t, lengths, out, mode);
    }
}